// round 15
// baseline (speedup 1.0000x reference)
#include <cuda_runtime.h>
#include <cuda_bf16.h>
#include <cstdint>

// ---------------------------------------------------------------------------
// Problem constants
// ---------------------------------------------------------------------------
#define B_SZ     8
#define N_PTS    131072
#define IN_C     64
#define OUT_C    64
#define STYLE_D  256
#define EPS_V    1e-8f

#define TILE_M   256          // points per CTA (two pipelined halves of 128)
#define HALF_M   128
#define THREADS  256          // 8 warps: 4 m-groups x 2 n-groups

// Per-batch modulated weights, bf16-split, linear [o][k] (64x64 each)
__device__ __align__(16) __nv_bfloat16 g_Whi[B_SZ][OUT_C * IN_C];
__device__ __align__(16) __nv_bfloat16 g_Wlo[B_SZ][OUT_C * IN_C];

// ---------------------------------------------------------------------------
// Kernel A: build weights, split to bf16 hi/lo. Negligible cost.
// ---------------------------------------------------------------------------
__global__ void modw_kernel(const float* __restrict__ style,
                            const float* __restrict__ weight,
                            const float* __restrict__ mod_weight,
                            const float* __restrict__ mod_bias) {
    const int b = blockIdx.x;
    const int t = threadIdx.x;             // 0..63 = output channel o
    __shared__ float s_sh[IN_C];

    const float mod_scale = 0.0625f;       // 1/sqrt(256)
    const float* st = style + b * STYLE_D;
    const float* mw = mod_weight + t * STYLE_D;
    float acc = 0.f;
    #pragma unroll 8
    for (int d = 0; d < STYLE_D; d += 4) {
        float4 a = *(const float4*)(st + d);
        float4 m = *(const float4*)(mw + d);
        acc += a.x * m.x + a.y * m.y + a.z * m.z + a.w * m.w;
    }
    s_sh[t] = acc * mod_scale + mod_bias[t] + 1.0f;
    __syncthreads();

    const float scale = 0.125f;            // 1/sqrt(64)
    const float* wr = weight + t * IN_C;
    float ss = 0.f;
    #pragma unroll 16
    for (int i = 0; i < IN_C; i++) {
        float v = scale * wr[i] * s_sh[i];
        ss += v * v;
    }
    float demod = rsqrtf(ss + EPS_V);
    #pragma unroll 16
    for (int i = 0; i < IN_C; i++) {
        float v = scale * wr[i] * s_sh[i] * demod;
        __nv_bfloat16 vh = __float2bfloat16(v);
        __nv_bfloat16 vl = __float2bfloat16(v - __bfloat162float(vh));
        g_Whi[b][t * IN_C + i] = vh;
        g_Wlo[b][t * IN_C + i] = vl;
    }
}

// ---------------------------------------------------------------------------
// Primitives (plain sm_80+ features; NO tcgen05 — harness compiles a
// compute_103 (non-'a') PTX stage where tcgen05 is rejected).
// ---------------------------------------------------------------------------
__device__ __forceinline__ uint32_t smem_u32(const void* p) {
    uint32_t a;
    asm("{ .reg .u64 t; cvta.to.shared.u64 t, %1; cvt.u32.u64 %0, t; }"
        : "=r"(a) : "l"(p));
    return a;
}

#define LDSM4(r, a) \
    asm volatile("ldmatrix.sync.aligned.m8n8.x4.shared.b16 {%0,%1,%2,%3}, [%4];" \
        : "=r"((r)[0]), "=r"((r)[1]), "=r"((r)[2]), "=r"((r)[3]) : "r"(a))

#define MMA16816(c, a, b0, b1) \
    asm volatile("mma.sync.aligned.m16n8k16.row.col.f32.bf16.bf16.f32 " \
        "{%0,%1,%2,%3}, {%4,%5,%6,%7}, {%8,%9}, {%0,%1,%2,%3};" \
        : "+f"((c)[0]), "+f"((c)[1]), "+f"((c)[2]), "+f"((c)[3]) \
        : "r"((a)[0]), "r"((a)[1]), "r"((a)[2]), "r"((a)[3]), \
          "r"(b0), "r"(b1))

#define CP_ASYNC16(sdst, gsrc) \
    asm volatile("cp.async.ca.shared.global [%0], [%1], 16;" \
        :: "r"(sdst), "l"(gsrc) : "memory")
#define CP_COMMIT()  asm volatile("cp.async.commit_group;" ::: "memory")
#define CP_WAIT1()   asm volatile("cp.async.wait_group 1;"  ::: "memory")
#define CP_WAIT0()   asm volatile("cp.async.wait_group 0;"  ::: "memory")

// Split one float2 (k-even, k-odd) into packed hi/lo bf16x2 fragment regs.
__device__ __forceinline__ void split2(float2 v, uint32_t& h, uint32_t& l) {
    __nv_bfloat162 hb = __floats2bfloat162_rn(v.x, v.y);
    uint32_t hu = *(uint32_t*)&hb;
    float xh = __uint_as_float(hu << 16);
    float yh = __uint_as_float(hu & 0xffff0000u);
    __nv_bfloat162 lb = __floats2bfloat162_rn(v.x - xh, v.y - yh);
    h = hu;
    l = *(uint32_t*)&lb;
}

// ---------------------------------------------------------------------------
// SMEM layout.
//  W images (bf16 hi/lo): pitch 144B, conflict-free ldmatrix.
//  X stage buffers: fp32, pitch 272B (68 floats) — rows walk bank groups.
//  Output overlay aliases the consumed X buffer (same 272B pitch).
// ---------------------------------------------------------------------------
#define W_PITCH   144
#define XPITCHB   272
#define OUT_PITCH 68
#define SM_W_HI   0
#define SM_W_LO   (OUT_C * W_PITCH)                  //  9216
#define SM_XF0    (SM_W_LO + OUT_C * W_PITCH)        // 18432
#define SM_XF1    (SM_XF0 + HALF_M * XPITCHB)        // 53248
#define SM_TOTAL  (SM_XF1 + HALF_M * XPITCHB)        // 88064

// ---------------------------------------------------------------------------
// Kernel B: bf16x3 GEMM via mma.sync, double-buffered cp.async pipeline.
// D = Xhi*Whi + Xlo*Whi + Xhi*Wlo. A split done in registers at consumption.
// ---------------------------------------------------------------------------
__global__ __launch_bounds__(THREADS, 2)
void modconv_mma(const float* __restrict__ x,
                 const float* __restrict__ bias,
                 float* __restrict__ out) {
    extern __shared__ __align__(16) char smem[];
    const uint32_t sb = smem_u32(smem);
    const int tid = threadIdx.x;
    const int wid = tid >> 5;
    const int lid = tid & 31;
    const int b   = blockIdx.y;
    const long gbase = ((long)b * N_PTS + (long)blockIdx.x * TILE_M) * IN_C;

    // ---- stage W (cp.async) + X half0 (cp.async fp32) -> group G0 ----
    {
        const char* whi = (const char*)g_Whi[b];
        const char* wlo = (const char*)g_Wlo[b];
        #pragma unroll
        for (int it = 0; it < 2; it++) {
            int idx = tid + it * THREADS;            // 0..511
            int o = idx >> 3, c = idx & 7;
            CP_ASYNC16(sb + SM_W_HI + o * W_PITCH + c * 16, whi + idx * 16);
            CP_ASYNC16(sb + SM_W_LO + o * W_PITCH + c * 16, wlo + idx * 16);
        }
        const char* xg = (const char*)(x + gbase);
        #pragma unroll
        for (int it = 0; it < 8; it++) {
            int idx = tid + it * THREADS;            // 16B chunk 0..2047
            int p = idx >> 4, c = idx & 15;
            CP_ASYNC16(sb + SM_XF0 + p * XPITCHB + c * 16, xg + idx * 16);
        }
        CP_COMMIT();                                 // G0
        const char* xg1 = xg + HALF_M * IN_C * 4;
        #pragma unroll
        for (int it = 0; it < 8; it++) {
            int idx = tid + it * THREADS;
            int p = idx >> 4, c = idx & 15;
            CP_ASYNC16(sb + SM_XF1 + p * XPITCHB + c * 16, xg1 + idx * 16);
        }
        CP_COMMIT();                                 // G1
    }

    // ---- warp tiling / lane mapping ----
    const int mBase = (wid & 3) * 32;                // point rows (within half)
    const int oBase = (wid >> 2) * 32;               // output cols
    const int g  = lid >> 2;                         // A fragment row in group
    const int t4 = lid & 3;                          // A fragment col pair
    const int mi = lid >> 3;
    const int l7 = lid & 7;
    const int w_row = (mi >> 1) * 8 + l7;            // W ldmatrix lane rows
    const int w_kh  = mi & 1;

    CP_WAIT1();                                      // G0 (W + X0) arrived
    __syncthreads();

    #pragma unroll
    for (int h = 0; h < 2; h++) {
        const int xoff = h ? SM_XF1 : SM_XF0;
        // per-thread A base: BYTE OFFSET from generic smem pointer
        // (R14 bug: dereferenced a cvta.to.shared 32-bit address as a
        //  generic pointer -> illegal access. Use smem + offset instead.)
        const int abase = xoff + (mBase + g) * XPITCHB + t4 * 8;

        float C[2][4][4];
        #pragma unroll
        for (int i = 0; i < 2; i++)
            #pragma unroll
            for (int j = 0; j < 4; j++)
                #pragma unroll
                for (int q = 0; q < 4; q++) C[i][j][q] = 0.f;

        #pragma unroll
        for (int ks = 0; ks < 4; ks++) {
            uint32_t AH[2][4], AL[2][4], WH[2][4], WL[2][4];
            #pragma unroll
            for (int mf = 0; mf < 2; mf++) {
                const int ab = abase + mf * (16 * XPITCHB) + ks * 64;
                float2 v00 = *(const float2*)(smem + ab);                    // (g,   2t)
                float2 v10 = *(const float2*)(smem + ab + 8 * XPITCHB);      // (g+8, 2t)
                float2 v01 = *(const float2*)(smem + ab + 32);               // (g,   2t+8)
                float2 v11 = *(const float2*)(smem + ab + 8 * XPITCHB + 32); // (g+8, 2t+8)
                split2(v00, AH[mf][0], AL[mf][0]);
                split2(v10, AH[mf][1], AL[mf][1]);
                split2(v01, AH[mf][2], AL[mf][2]);
                split2(v11, AH[mf][3], AL[mf][3]);
            }
            #pragma unroll
            for (int nb = 0; nb < 2; nb++) {
                uint32_t woff = (oBase + nb * 16 + w_row) * W_PITCH
                              + ks * 32 + w_kh * 16;
                LDSM4(WH[nb], sb + SM_W_HI + woff);
                LDSM4(WL[nb], sb + SM_W_LO + woff);
            }
            #pragma unroll
            for (int mf = 0; mf < 2; mf++)
                #pragma unroll
                for (int nf = 0; nf < 4; nf++) {
                    const int nb = nf >> 1, sel = (nf & 1) * 2;
                    float* c = C[mf][nf];
                    MMA16816(c, AH[mf], WH[nb][sel], WH[nb][sel + 1]);
                    MMA16816(c, AL[mf], WH[nb][sel], WH[nb][sel + 1]);
                    MMA16816(c, AH[mf], WL[nb][sel], WL[nb][sel + 1]);
                }
        }

        // ---- epilogue: overlay aliases this half's X buffer ----
        __syncthreads();                   // all warps done reading XF[h]
        {
            float* ovl = (float*)(smem + xoff);
            const int gg = lid >> 2, t2 = (lid & 3) * 2;
            #pragma unroll
            for (int mf = 0; mf < 2; mf++)
                #pragma unroll
                for (int nf = 0; nf < 4; nf++) {
                    const int col = oBase + nf * 8 + t2;
                    const float b0 = __ldg(bias + col);
                    const float b1 = __ldg(bias + col + 1);
                    const int r0 = mBase + mf * 16 + gg;
                    float* c = C[mf][nf];
                    *(float2*)(ovl + r0 * OUT_PITCH + col) =
                        make_float2(c[0] + b0, c[1] + b1);
                    *(float2*)(ovl + (r0 + 8) * OUT_PITCH + col) =
                        make_float2(c[2] + b0, c[3] + b1);
                }
        }
        __syncthreads();
        {
            const float* ovl = (const float*)(smem + xoff);
            float4* out4 = (float4*)(out + gbase + (long)h * HALF_M * IN_C);
            #pragma unroll
            for (int it = 0; it < 8; it++) {
                int idx = tid + it * THREADS;        // 0..2047
                int p = idx >> 4, c = idx & 15;
                out4[idx] = *(const float4*)(ovl + p * OUT_PITCH + c * 4);
            }
        }
        if (h == 0) {
            CP_WAIT0();                              // X1 arrived (overlapped)
            __syncthreads();
        }
    }
}

// ---------------------------------------------------------------------------
// Launch
// inputs: 0=x, 1=style, 2=weight, 3=bias, 4=mod_weight, 5=mod_bias
// ---------------------------------------------------------------------------
extern "C" void kernel_launch(void* const* d_in, const int* in_sizes, int n_in,
                              void* d_out, int out_size) {
    const float* x          = (const float*)d_in[0];
    const float* style      = (const float*)d_in[1];
    const float* weight     = (const float*)d_in[2];
    const float* bias       = (const float*)d_in[3];
    const float* mod_weight = (const float*)d_in[4];
    const float* mod_bias   = (const float*)d_in[5];
    float* out = (float*)d_out;

    cudaFuncSetAttribute(modconv_mma,
                         cudaFuncAttributeMaxDynamicSharedMemorySize, SM_TOTAL);

    modw_kernel<<<B_SZ, 64>>>(style, weight, mod_weight, mod_bias);

    dim3 grid(N_PTS / TILE_M, B_SZ);
    modconv_mma<<<grid, THREADS, SM_TOTAL>>>(x, bias, out);
}